// round 1
// baseline (speedup 1.0000x reference)
#include <cuda_runtime.h>
#include <math_constants.h>

// Chamfer distance, B=16 events, P=Q=4096 points, 3D.
// loss = (1/B) * sum_b [ mean_p min_q d(p,q) + mean_q min_p d(p,q) ]
// with d = |x|^2 + |y|^2 - 2 x.y  (matches reference formula).
// Strategy: brute force, both directions as grid.z=0/1 of one kernel.
// Inner loop packed with Blackwell f32x2 FMA: 3 FFMA2 per 2 candidate points.

#define NB 16
#define NP 4096
#define THREADS 128
#define RPT 2
#define ROWS (THREADS * RPT)          // 256 query rows per block
#define CHUNKS (NP / ROWS)            // 16 chunks per event
#define TQ 256                        // candidate tile size (smem)
#define NPART (CHUNKS * NB * 2)       // 512 partial sums

__device__ float g_partials[NPART];

typedef unsigned long long u64;

__device__ __forceinline__ u64 pack2(float lo, float hi) {
    u64 r;
    asm("mov.b64 %0, {%1, %2};" : "=l"(r) : "f"(lo), "f"(hi));
    return r;
}
__device__ __forceinline__ u64 ffma2(u64 a, u64 b, u64 c) {
    u64 r;
    asm("fma.rn.f32x2 %0, %1, %2, %3;" : "=l"(r) : "l"(a), "l"(b), "l"(c));
    return r;
}
__device__ __forceinline__ void unpack2(u64 v, float& lo, float& hi) {
    asm("mov.b64 {%0, %1}, %2;" : "=f"(lo), "=f"(hi) : "l"(v));
}

__global__ __launch_bounds__(THREADS)
void chamfer_kernel(const float* __restrict__ gen,
                    const float* __restrict__ label) {
    // Candidate tile: scaled coords (-2*y) and norms (y^2), pair-packable.
    __shared__ __align__(16) float sqx[TQ];
    __shared__ __align__(16) float sqy[TQ];
    __shared__ __align__(16) float sqz[TQ];
    __shared__ __align__(16) float sqn[TQ];
    __shared__ float red[THREADS / 32];

    const int dir   = blockIdx.z;   // 0: gen->gt, 1: gt->gen
    const int b     = blockIdx.y;
    const int chunk = blockIdx.x;
    const int t     = threadIdx.x;

    const float inv128 = 1.0f / 128.0f;

    // ---- load query rows (register resident) ----
    u64 xp0[RPT], xp1[RPT], xp2[RPT];
    float xn[RPT], mlo[RPT], mhi[RPT];
#pragma unroll
    for (int r = 0; r < RPT; r++) {
        int row = b * NP + chunk * ROWS + r * THREADS + t;
        float px, py, pz;
        if (dir == 0) {
            const float* s = gen + (size_t)row * 3;
            px = s[0]; py = s[1]; pz = s[2];
        } else {
            const float* s = label + (size_t)row * 5 + 1;
            px = (s[0] - 128.0f) * inv128;
            py = (s[1] - 128.0f) * inv128;
            pz = (s[2] - 128.0f) * inv128;
        }
        xn[r] = px * px + py * py + pz * pz;
        xp0[r] = pack2(px, px);
        xp1[r] = pack2(py, py);
        xp2[r] = pack2(pz, pz);
        mlo[r] = CUDART_INF_F;
        mhi[r] = CUDART_INF_F;
    }

    // ---- sweep candidate points in smem tiles ----
    for (int tile = 0; tile < NP; tile += TQ) {
        __syncthreads();
#pragma unroll
        for (int p = t; p < TQ; p += THREADS) {
            int idx = b * NP + tile + p;
            float cx, cy, cz;
            if (dir == 0) {
                const float* s = label + (size_t)idx * 5 + 1;
                cx = (s[0] - 128.0f) * inv128;
                cy = (s[1] - 128.0f) * inv128;
                cz = (s[2] - 128.0f) * inv128;
            } else {
                const float* s = gen + (size_t)idx * 3;
                cx = s[0]; cy = s[1]; cz = s[2];
            }
            sqn[p] = cx * cx + cy * cy + cz * cz;
            sqx[p] = -2.0f * cx;
            sqy[p] = -2.0f * cy;
            sqz[p] = -2.0f * cz;
        }
        __syncthreads();

        const u64* cqx = (const u64*)sqx;
        const u64* cqy = (const u64*)sqy;
        const u64* cqz = (const u64*)sqz;
        const u64* cqn = (const u64*)sqn;

#pragma unroll 4
        for (int j = 0; j < TQ / 2; j++) {
            u64 ax = cqx[j], ay = cqy[j], az = cqz[j], an = cqn[j];
#pragma unroll
            for (int r = 0; r < RPT; r++) {
                // d' = y^2 + (-2y).x  packed for two candidates
                u64 d = ffma2(xp2[r], az,
                        ffma2(xp1[r], ay,
                        ffma2(xp0[r], ax, an)));
                float lo, hi;
                unpack2(d, lo, hi);
                mlo[r] = fminf(mlo[r], lo);
                mhi[r] = fminf(mhi[r], hi);
            }
        }
    }

    // ---- per-thread finalize: min d = x^2 + min(d') ----
    float s = 0.0f;
#pragma unroll
    for (int r = 0; r < RPT; r++)
        s += fminf(mlo[r], mhi[r]) + xn[r];

    // ---- deterministic block reduction ----
#pragma unroll
    for (int o = 16; o > 0; o >>= 1)
        s += __shfl_down_sync(0xffffffffu, s, o);
    if ((t & 31) == 0) red[t >> 5] = s;
    __syncthreads();
    if (t == 0) {
        float tot = 0.0f;
#pragma unroll
        for (int w = 0; w < THREADS / 32; w++) tot += red[w];
        int lin = (blockIdx.z * gridDim.y + blockIdx.y) * gridDim.x + blockIdx.x;
        g_partials[lin] = tot;
    }
}

__global__ void finalize_kernel(float* __restrict__ out) {
    if (threadIdx.x == 0 && blockIdx.x == 0) {
        float s = 0.0f;
        for (int i = 0; i < NPART; i++) s += g_partials[i];
        // / P per event, then / B:  1 / (4096 * 16)
        out[0] = s * (1.0f / 65536.0f);
    }
}

extern "C" void kernel_launch(void* const* d_in, const int* in_sizes, int n_in,
                              void* d_out, int out_size) {
    const float* gen   = (const float*)d_in[0];  // [B*P, 3]
    // d_in[1] = batch_gen (int32), unused: segments are contiguous equal-size
    const float* label = (const float*)d_in[2];  // [B*Q, 5]
    float* out = (float*)d_out;

    dim3 grid(CHUNKS, NB, 2);
    chamfer_kernel<<<grid, THREADS>>>(gen, label);
    finalize_kernel<<<1, 32>>>(out);
}

// round 2
// speedup vs baseline: 1.1443x; 1.1443x over previous
#include <cuda_runtime.h>
#include <math_constants.h>

// Chamfer distance, B=16 events, P=Q=4096, 3D.
// d = |x|^2 + |y|^2 - 2 x.y ; loss = (1/B) sum_b (mean_p min_q + mean_q min_p)
// R2: RPT=4, 32B-quad candidate tile (2x LDS.128/iter), whole-event smem
// (2x32KB passes), fused deterministic finalize (last-block reduction).

#define NB 16
#define NP 4096
#define THREADS 128
#define RPT 4
#define ROWS (THREADS * RPT)          // 512 query rows per block
#define CHUNKS (NP / ROWS)            // 8
#define TQ 2048                       // candidates per smem pass (32KB)
#define NPASS (NP / TQ)               // 2
#define NPART (CHUNKS * NB * 2)       // 256 partials

__device__ float g_partials[NPART];
__device__ unsigned int g_sync;       // zero-init; reset by last block each call

typedef unsigned long long u64;

__device__ __forceinline__ u64 pack2(float lo, float hi) {
    u64 r;
    asm("mov.b64 %0, {%1, %2};" : "=l"(r) : "f"(lo), "f"(hi));
    return r;
}
__device__ __forceinline__ u64 ffma2(u64 a, u64 b, u64 c) {
    u64 r;
    asm("fma.rn.f32x2 %0, %1, %2, %3;" : "=l"(r) : "l"(a), "l"(b), "l"(c));
    return r;
}
__device__ __forceinline__ void unpack2(u64 v, float& lo, float& hi) {
    asm("mov.b64 {%0, %1}, %2;" : "=f"(lo), "=f"(hi) : "l"(v));
}

__global__ __launch_bounds__(THREADS)
void chamfer_kernel(const float* __restrict__ gen,
                    const float* __restrict__ label,
                    float* __restrict__ out) {
    // Candidate quad per pair j: {(-2x0,-2x1),(-2y0,-2y1),(-2z0,-2z1),(n0,n1)}
    __shared__ __align__(16) float tile[TQ / 2][8];   // 32 KB
    __shared__ float red[THREADS / 32];
    __shared__ unsigned int is_last;

    const int dir   = blockIdx.z;   // 0: gen->gt, 1: gt->gen
    const int b     = blockIdx.y;
    const int chunk = blockIdx.x;
    const int t     = threadIdx.x;

    const float inv128 = 1.0f / 128.0f;

    // ---- query rows, register resident ----
    u64 xp0[RPT], xp1[RPT], xp2[RPT];
    float xn[RPT], mlo[RPT], mhi[RPT];
#pragma unroll
    for (int r = 0; r < RPT; r++) {
        int row = b * NP + chunk * ROWS + r * THREADS + t;
        float px, py, pz;
        if (dir == 0) {
            const float* s = gen + (size_t)row * 3;
            px = s[0]; py = s[1]; pz = s[2];
        } else {
            const float* s = label + (size_t)row * 5 + 1;
            px = (s[0] - 128.0f) * inv128;
            py = (s[1] - 128.0f) * inv128;
            pz = (s[2] - 128.0f) * inv128;
        }
        xn[r] = px * px + py * py + pz * pz;
        xp0[r] = pack2(px, px);
        xp1[r] = pack2(py, py);
        xp2[r] = pack2(pz, pz);
        mlo[r] = CUDART_INF_F;
        mhi[r] = CUDART_INF_F;
    }

    // ---- sweep candidates in NPASS big passes ----
    for (int pass = 0; pass < NPASS; pass++) {
        __syncthreads();
#pragma unroll
        for (int p = t; p < TQ; p += THREADS) {
            int idx = b * NP + pass * TQ + p;
            float cx, cy, cz;
            if (dir == 0) {
                const float* s = label + (size_t)idx * 5 + 1;
                cx = (s[0] - 128.0f) * inv128;
                cy = (s[1] - 128.0f) * inv128;
                cz = (s[2] - 128.0f) * inv128;
            } else {
                const float* s = gen + (size_t)idx * 3;
                cx = s[0]; cy = s[1]; cz = s[2];
            }
            int j = p >> 1, h = p & 1;
            tile[j][0 + h] = -2.0f * cx;
            tile[j][2 + h] = -2.0f * cy;
            tile[j][4 + h] = -2.0f * cz;
            tile[j][6 + h] = cx * cx + cy * cy + cz * cz;
        }
        __syncthreads();

        const ulonglong2* tp = (const ulonglong2*)tile;

#pragma unroll 8
        for (int j = 0; j < TQ / 2; j++) {
            ulonglong2 c0 = tp[j * 2 + 0];   // {ax, ay}
            ulonglong2 c1 = tp[j * 2 + 1];   // {az, an}
#pragma unroll
            for (int r = 0; r < RPT; r++) {
                u64 d = ffma2(xp2[r], c1.x,
                        ffma2(xp1[r], c0.y,
                        ffma2(xp0[r], c0.x, c1.y)));
                float lo, hi;
                unpack2(d, lo, hi);
                mlo[r] = fminf(mlo[r], lo);
                mhi[r] = fminf(mhi[r], hi);
            }
        }
    }

    // ---- per-thread finalize: min d = x^2 + min(d') ----
    float s = 0.0f;
#pragma unroll
    for (int r = 0; r < RPT; r++)
        s += fminf(mlo[r], mhi[r]) + xn[r];

    // ---- deterministic block reduction ----
#pragma unroll
    for (int o = 16; o > 0; o >>= 1)
        s += __shfl_down_sync(0xffffffffu, s, o);
    if ((t & 31) == 0) red[t >> 5] = s;
    __syncthreads();
    if (t == 0) {
        float tot = 0.0f;
#pragma unroll
        for (int w = 0; w < THREADS / 32; w++) tot += red[w];
        int lin = (blockIdx.z * gridDim.y + blockIdx.y) * gridDim.x + blockIdx.x;
        g_partials[lin] = tot;
        __threadfence();
        unsigned int v = atomicAdd(&g_sync, 1u);
        is_last = (v == (unsigned int)(NPART - 1)) ? 1u : 0u;
    }
    __syncthreads();

    // ---- last block: fixed-order global reduction (deterministic) ----
    if (is_last) {
        __threadfence();
        float ps = __ldcg(&g_partials[t]) + __ldcg(&g_partials[t + THREADS]);
#pragma unroll
        for (int o = 16; o > 0; o >>= 1)
            ps += __shfl_down_sync(0xffffffffu, ps, o);
        if ((t & 31) == 0) red[t >> 5] = ps;
        __syncthreads();
        if (t == 0) {
            float tot = 0.0f;
#pragma unroll
            for (int w = 0; w < THREADS / 32; w++) tot += red[w];
            out[0] = tot * (1.0f / 65536.0f);   // / (P * B)
            g_sync = 0u;                        // reset for next call
        }
    }
}

extern "C" void kernel_launch(void* const* d_in, const int* in_sizes, int n_in,
                              void* d_out, int out_size) {
    const float* gen   = (const float*)d_in[0];  // [B*P, 3]
    // d_in[1] = batch_gen (int32), unused: contiguous equal segments
    const float* label = (const float*)d_in[2];  // [B*Q, 5]
    float* out = (float*)d_out;

    dim3 grid(CHUNKS, NB, 2);
    chamfer_kernel<<<grid, THREADS>>>(gen, label, out);
}